// round 11
// baseline (speedup 1.0000x reference)
#include <cuda_runtime.h>

// ---------------- problem constants (fixed by setup_inputs) ----------------
#define NT      16384          // hidden tokens (B*S)
#define NGTOK   64             // global tokens (real_b*G)
#define MROWS   16448          // NT + NGTOK
#define DMODEL  768
#define NHEAD   12
#define DHEAD   64
#define BATCH   32
#define SEQ     512
#define GTOK    16
#define NCTX    8
#define REALB   4
#define CTX_ELEMS (BATCH*SEQ*DMODEL)   // 12582912

// ---------------- scratch: Q/K/V in [B,H,S,DH] layout ----------------------
__device__ __align__(16) float d_Q [NT*DMODEL];
__device__ __align__(16) float d_Kb[NT*DMODEL];
__device__ __align__(16) float d_Vb[NT*DMODEL];
__device__ __align__(16) float d_GQ[NGTOK*DMODEL];   // [rb,H,G,DH]
__device__ __align__(16) float d_GK[NGTOK*DMODEL];
__device__ __align__(16) float d_GV[NGTOK*DMODEL];

// ============================================================================
// Fused QKV projection: C[M=16448, N=2304] = X @ [Wq|Wk|Wv] + bias
// Rows <16384 come from hidden_states, rest from global_tokens_embed.
// Epilogue scatters into [B,H,S,DH] / [rb,H,G,DH] layout buffers.
// Classic SGEMM: BM=BN=128, BK=16, 256 threads, 8x8 per thread.
// ============================================================================
__global__ __launch_bounds__(256) void qkv_gemm(
    const float* __restrict__ hs, const float* __restrict__ gte,
    const float* __restrict__ Wq, const float* __restrict__ Wk,
    const float* __restrict__ Wv,
    const float* __restrict__ bq, const float* __restrict__ bk,
    const float* __restrict__ bv)
{
    __shared__ __align__(16) float As[16][128];   // A transposed: As[k][m]
    __shared__ __align__(16) float Bs[16][128];   // Bs[k][n]

    const int tid = threadIdx.x;
    const int m0  = blockIdx.y * 128;
    const int n0  = blockIdx.x * 128;
    const int whichW = n0 / 768;                 // 0=Q 1=K 2=V (128 | 768)
    const float* __restrict__ W    = (whichW==0) ? Wq : (whichW==1) ? Wk : Wv;
    const float* __restrict__ bias = (whichW==0) ? bq : (whichW==1) ? bk : bv;
    const int wc0 = n0 - whichW*768;

    const int tr = tid >> 4;    // 0..15 -> rows tr*8..tr*8+7
    const int tc = tid & 15;    // 0..15 -> cols tc*8..tc*8+7

    float acc[8][8];
    #pragma unroll
    for (int i=0;i<8;i++)
        #pragma unroll
        for (int j=0;j<8;j++) acc[i][j] = 0.f;

    for (int k0 = 0; k0 < 768; k0 += 16) {
        #pragma unroll
        for (int ld = 0; ld < 2; ld++) {
            int f = tid + ld*256;               // 0..511 float4 slots
            // --- A tile: 128 rows x 16 k, store transposed ---
            int r  = f >> 2;
            int c4 = (f & 3) << 2;
            int gr = m0 + r;
            float4 v = make_float4(0.f,0.f,0.f,0.f);
            if (gr < MROWS) {
                const float* src = (gr < NT)
                    ? (hs  + (size_t)gr*768       + k0 + c4)
                    : (gte + (size_t)(gr-NT)*768  + k0 + c4);
                v = *(const float4*)src;
            }
            As[c4+0][r]=v.x; As[c4+1][r]=v.y; As[c4+2][r]=v.z; As[c4+3][r]=v.w;
            // --- B tile: 16 k x 128 n ---
            int rb_ = f >> 5;
            int cb  = (f & 31) << 2;
            *(float4*)&Bs[rb_][cb] =
                *(const float4*)(W + (size_t)(k0+rb_)*768 + wc0 + cb);
        }
        __syncthreads();
        #pragma unroll
        for (int kk = 0; kk < 16; kk++) {
            float4 a0 = *(const float4*)&As[kk][tr*8];
            float4 a1 = *(const float4*)&As[kk][tr*8+4];
            float4 b0 = *(const float4*)&Bs[kk][tc*8];
            float4 b1 = *(const float4*)&Bs[kk][tc*8+4];
            float ar[8] = {a0.x,a0.y,a0.z,a0.w,a1.x,a1.y,a1.z,a1.w};
            float br[8] = {b0.x,b0.y,b0.z,b0.w,b1.x,b1.y,b1.z,b1.w};
            #pragma unroll
            for (int i=0;i<8;i++)
                #pragma unroll
                for (int j=0;j<8;j++) acc[i][j] += ar[i]*br[j];
        }
        __syncthreads();
    }

    const int hcol = wc0 + tc*8;     // 0..767, 8-aligned -> one head
    const int h = hcol >> 6;
    const int d = hcol & 63;
    float bb[8];
    #pragma unroll
    for (int j=0;j<8;j++) bb[j] = bias[hcol+j];

    #pragma unroll
    for (int i=0;i<8;i++) {
        int gr = m0 + tr*8 + i;
        if (gr >= MROWS) continue;
        float* dst;
        size_t idx;
        if (gr < NT) {
            int b = gr >> 9, s = gr & 511;
            dst = (whichW==0) ? d_Q : (whichW==1) ? d_Kb : d_Vb;
            idx = (size_t)(b*NHEAD + h)*(SEQ*DHEAD) + (size_t)s*DHEAD + d;
        } else {
            int t = gr - NT;
            int rb_ = t >> 4, g = t & 15;
            dst = (whichW==0) ? d_GQ : (whichW==1) ? d_GK : d_GV;
            idx = (size_t)(rb_*NHEAD + h)*(GTOK*DHEAD) + (size_t)g*DHEAD + d;
        }
        float4 v0 = make_float4(acc[i][0]+bb[0], acc[i][1]+bb[1],
                                acc[i][2]+bb[2], acc[i][3]+bb[3]);
        float4 v1 = make_float4(acc[i][4]+bb[4], acc[i][5]+bb[5],
                                acc[i][6]+bb[6], acc[i][7]+bb[7]);
        *(float4*)(dst + idx)     = v0;
        *(float4*)(dst + idx + 4) = v1;
    }
}

// ============================================================================
// Local attention: for each (b,h), 512 queries attend to [16 global + 512 own]
// keys. Flash-style online softmax; thread-per-query, 128 queries per block,
// key chunks of 16 staged in smem (LDS.128 broadcast reads).
// grid = B*H*4 = 1536, block = 128
// ============================================================================
#define QPAD 68
__global__ __launch_bounds__(128) void local_attn(
    const float* __restrict__ am, float* __restrict__ out)
{
    __shared__ __align__(16) float Qs[128][QPAD];
    __shared__ __align__(16) float Ks[16][64];
    __shared__ __align__(16) float Vs[16][64];

    const int bx = blockIdx.x;
    const int qt = bx & 3;
    const int bh = bx >> 2;
    const int h  = bh % NHEAD;
    const int b  = bh / NHEAD;
    const int rb = b >> 3;                 // b / NCTX
    const int tid = threadIdx.x;

    // Load 128x64 Q tile (contiguous 32KB region), coalesced
    const float* Qsrc = d_Q + (size_t)(b*NHEAD + h)*(SEQ*DHEAD) + (size_t)qt*8192;
    for (int i = tid; i < 2048; i += 128) {
        int r = i >> 4, c4 = (i & 15) << 2;
        *(float4*)&Qs[r][c4] = *(const float4*)(Qsrc + r*64 + c4);
    }
    __syncthreads();

    float qreg[64];
    #pragma unroll
    for (int d4 = 0; d4 < 64; d4 += 4) {
        float4 v = *(const float4*)&Qs[tid][d4];
        qreg[d4]=v.x; qreg[d4+1]=v.y; qreg[d4+2]=v.z; qreg[d4+3]=v.w;
    }

    float m = -1e30f, l = 0.f;
    float acc[64];
    #pragma unroll
    for (int d = 0; d < 64; d++) acc[d] = 0.f;

    const float* Kbase = d_Kb + (size_t)(b*NHEAD + h)*(SEQ*DHEAD);
    const float* Vbase = d_Vb + (size_t)(b*NHEAD + h)*(SEQ*DHEAD);
    const float* GKb   = d_GK + (size_t)(rb*NHEAD + h)*(GTOK*DHEAD);
    const float* GVb   = d_GV + (size_t)(rb*NHEAD + h)*(GTOK*DHEAD);
    const float* amb   = am + (size_t)b*SEQ;

    for (int c = 0; c < 33; c++) {          // chunk 0 = 16 global keys
        const float* ksrc = (c==0) ? GKb : Kbase + (size_t)(c-1)*1024;
        const float* vsrc = (c==0) ? GVb : Vbase + (size_t)(c-1)*1024;
        __syncthreads();
        for (int i = tid; i < 256; i += 128) {
            int r = i >> 4, c4 = (i & 15) << 2;
            *(float4*)&Ks[r][c4] = *(const float4*)(ksrc + r*64 + c4);
            *(float4*)&Vs[r][c4] = *(const float4*)(vsrc + r*64 + c4);
        }
        __syncthreads();

        float p[16];
        #pragma unroll
        for (int j = 0; j < 16; j++) {
            float s = 0.f;
            #pragma unroll
            for (int d4 = 0; d4 < 64; d4 += 4) {
                float4 kv = *(const float4*)&Ks[j][d4];
                s += qreg[d4]*kv.x + qreg[d4+1]*kv.y
                   + qreg[d4+2]*kv.z + qreg[d4+3]*kv.w;
            }
            p[j] = s*0.125f + ((c==0) ? 0.f : amb[(c-1)*16 + j]);
        }
        float cmax = p[0];
        #pragma unroll
        for (int j = 1; j < 16; j++) cmax = fmaxf(cmax, p[j]);
        float mn   = fmaxf(m, cmax);
        float corr = __expf(m - mn);
        m = mn; l *= corr;
        #pragma unroll
        for (int d = 0; d < 64; d++) acc[d] *= corr;
        #pragma unroll
        for (int j = 0; j < 16; j++) {
            float e = __expf(p[j] - mn);
            l += e;
            #pragma unroll
            for (int d4 = 0; d4 < 64; d4 += 4) {
                float4 vv = *(const float4*)&Vs[j][d4];
                acc[d4]   += e*vv.x;  acc[d4+1] += e*vv.y;
                acc[d4+2] += e*vv.z;  acc[d4+3] += e*vv.w;
            }
        }
    }

    float inv = 1.f / l;
    __syncthreads();
    #pragma unroll
    for (int d = 0; d < 64; d++) Qs[tid][d] = acc[d]*inv;
    __syncthreads();

    // coalesced store: ctx[b, s, h*64+d]
    float* ob = out + ((size_t)b*SEQ + (size_t)qt*128)*DMODEL + h*64;
    for (int i = tid; i < 2048; i += 128) {
        int r = i >> 4, c4 = (i & 15) << 2;
        *(float4*)(ob + (size_t)r*DMODEL + c4) = *(const float4*)&Qs[r][c4];
    }
}

// ============================================================================
// Global-token attention: (rb,h) x 16 queries over 16 global + 4096 packed
// keys. Warp per query, keys split across lanes (online softmax per lane),
// shuffle-tree merge at the end. grid = RB*H*4 = 192, block = 128 (4 warps).
// ============================================================================
#define KPAD 72
__global__ __launch_bounds__(128) void global_attn(
    const float* __restrict__ am, float* __restrict__ out)
{
    __shared__ __align__(16) float Qs[4][64];
    __shared__ __align__(16) float Ks[64][KPAD];
    __shared__ __align__(16) float Vs[64][KPAD];

    const int bx  = blockIdx.x;
    const int qg  = bx & 3;                  // group of 4 queries
    const int rbh = bx >> 2;
    const int h   = rbh % NHEAD;
    const int rb  = rbh / NHEAD;
    const int tid = threadIdx.x;
    const int w    = tid >> 5;
    const int lane = tid & 31;

    if (tid < 64) {
        const float* GQb = d_GQ + (size_t)(rb*NHEAD + h)*(GTOK*DHEAD) + qg*256;
        *(float4*)&Qs[tid>>4][(tid&15)<<2] = *(const float4*)(GQb + tid*4);
    }

    float m = -1e30f, l = 0.f;
    float acc[64];
    #pragma unroll
    for (int d = 0; d < 64; d++) acc[d] = 0.f;

    // ---- chunk of 16 global keys ----
    {
        const float* GKb = d_GK + (size_t)(rb*NHEAD + h)*(GTOK*DHEAD);
        const float* GVb = d_GV + (size_t)(rb*NHEAD + h)*(GTOK*DHEAD);
        for (int i = tid; i < 256; i += 128) {
            int r = i >> 4, c4 = (i & 15) << 2;
            *(float4*)&Ks[r][c4] = *(const float4*)(GKb + r*64 + c4);
            *(float4*)&Vs[r][c4] = *(const float4*)(GVb + r*64 + c4);
        }
        __syncthreads();
        if (lane < 16) {
            int j = lane;
            float s = 0.f;
            #pragma unroll
            for (int d4 = 0; d4 < 64; d4 += 4) {
                float4 kv = *(const float4*)&Ks[j][d4];
                float4 qv = *(const float4*)&Qs[w][d4];
                s += qv.x*kv.x + qv.y*kv.y + qv.z*kv.z + qv.w*kv.w;
            }
            s = s*0.125f;                    // global keys: mask = 0
            float mn = fmaxf(m, s);
            float corr = __expf(m - mn);
            float e    = __expf(s - mn);
            l = l*corr + e;
            #pragma unroll
            for (int d4 = 0; d4 < 64; d4 += 4) {
                float4 vv = *(const float4*)&Vs[j][d4];
                acc[d4]   = acc[d4]  *corr + e*vv.x;
                acc[d4+1] = acc[d4+1]*corr + e*vv.y;
                acc[d4+2] = acc[d4+2]*corr + e*vv.z;
                acc[d4+3] = acc[d4+3]*corr + e*vv.w;
            }
            m = mn;
        }
    }

    // ---- 64 chunks of 64 packed-context keys ----
    for (int c = 0; c < 64; c++) {
        int t0   = c*64;
        int bloc = rb*NCTX + (t0 >> 9);
        int s0   = t0 & 511;
        const float* kb = d_Kb + (size_t)(bloc*NHEAD + h)*(SEQ*DHEAD) + (size_t)s0*64;
        const float* vb = d_Vb + (size_t)(bloc*NHEAD + h)*(SEQ*DHEAD) + (size_t)s0*64;
        __syncthreads();
        for (int i = tid; i < 1024; i += 128) {
            int r = i >> 4, c4 = (i & 15) << 2;
            *(float4*)&Ks[r][c4] = *(const float4*)(kb + r*64 + c4);
            *(float4*)&Vs[r][c4] = *(const float4*)(vb + r*64 + c4);
        }
        __syncthreads();
        #pragma unroll
        for (int half = 0; half < 2; half++) {
            int j = lane + half*32;
            float msk = am[(size_t)rb*4096 + t0 + j];
            float s = 0.f;
            #pragma unroll
            for (int d4 = 0; d4 < 64; d4 += 4) {
                float4 kv = *(const float4*)&Ks[j][d4];
                float4 qv = *(const float4*)&Qs[w][d4];
                s += qv.x*kv.x + qv.y*kv.y + qv.z*kv.z + qv.w*kv.w;
            }
            s = s*0.125f + msk;
            float mn   = fmaxf(m, s);
            float corr = __expf(m - mn);
            float e    = __expf(s - mn);
            l = l*corr + e;
            #pragma unroll
            for (int d4 = 0; d4 < 64; d4 += 4) {
                float4 vv = *(const float4*)&Vs[j][d4];
                acc[d4]   = acc[d4]  *corr + e*vv.x;
                acc[d4+1] = acc[d4+1]*corr + e*vv.y;
                acc[d4+2] = acc[d4+2]*corr + e*vv.z;
                acc[d4+3] = acc[d4+3]*corr + e*vv.w;
            }
            m = mn;
        }
    }

    // ---- merge (m, l, acc[64]) across the 32 lanes of this warp ----
    const unsigned FULL = 0xffffffffu;
    #pragma unroll
    for (int off = 16; off > 0; off >>= 1) {
        float mo = __shfl_down_sync(FULL, m, off);
        float lo = __shfl_down_sync(FULL, l, off);
        float mn = fmaxf(m, mo);
        float e1 = __expf(m - mn), e2 = __expf(mo - mn);
        l = l*e1 + lo*e2;
        m = mn;
        #pragma unroll
        for (int d = 0; d < 64; d++) {
            float ao = __shfl_down_sync(FULL, acc[d], off);
            acc[d] = acc[d]*e1 + ao*e2;
        }
    }

    if (lane == 0) {
        float inv = 1.f / l;
        int g = qg*4 + w;
        float* ob = out + (size_t)CTX_ELEMS + ((size_t)rb*GTOK + g)*DMODEL + h*64;
        #pragma unroll
        for (int d = 0; d < 64; d++) ob[d] = acc[d]*inv;
    }
}

// ============================================================================
extern "C" void kernel_launch(void* const* d_in, const int* in_sizes, int n_in,
                              void* d_out, int out_size) {
    const float* hs  = (const float*)d_in[0];   // hidden_states [32,512,768]
    const float* am  = (const float*)d_in[1];   // attention_mask [32,1,1,512]
    const float* gte = (const float*)d_in[2];   // global_tokens_embed [4,16,768]
    const float* Wq  = (const float*)d_in[3];
    const float* bq  = (const float*)d_in[4];
    const float* Wk  = (const float*)d_in[5];
    const float* bk  = (const float*)d_in[6];
    const float* Wv  = (const float*)d_in[7];
    const float* bv  = (const float*)d_in[8];
    // d_in[9] = num_ctx (fixed 8)
    float* out = (float*)d_out;

    dim3 gemm_grid(2304/128, (MROWS + 127)/128);   // 18 x 129
    qkv_gemm<<<gemm_grid, 256>>>(hs, gte, Wq, Wk, Wv, bq, bk, bv);
    local_attn<<<BATCH*NHEAD*4, 128>>>(am, out);
    global_attn<<<REALB*NHEAD*4, 128>>>(am, out);
}